// round 17
// baseline (speedup 1.0000x reference)
#include <cuda_runtime.h>
#include <cuda_bf16.h>
#include <math.h>
#include <stdint.h>

#define D       256
#define MROWS   32768        // B*C
#define EPS     1e-5f
#define BM      128
#define BN      64
#define BK      16
#define NCHUNK  (D / BK)     // 16
#define ARB     48           // smem A row bytes: 16 bf16 = 32B data + 16B pad
#define BRB     48           // smem B row bytes

// ---------------- device scratch (no allocation allowed) -------------------
__device__ float g_x0[(size_t)MROWS * D];
__device__ float g_x1[(size_t)MROWS * D];
__device__ __nv_bfloat16 g_wh[4 * D * D];   // W^T hi, per layer, [n][k]
__device__ __nv_bfloat16 g_wl[4 * D * D];   // W^T lo
__device__ float g_sum[D], g_sumsq[D], g_scale[D], g_shift[D];

// ---------------- helpers ---------------------------------------------------
__device__ __forceinline__ uint32_t smem_u32(const void* p) {
    uint32_t r;
    asm("{ .reg .u64 t; cvta.to.shared.u64 t, %1; cvt.u32.u64 %0, t; }"
        : "=r"(r) : "l"(p));
    return r;
}
__device__ __forceinline__ float gelu_exact(float x) {
    return 0.5f * x * erfcf(-0.70710678118654752440f * x);
}
__device__ __forceinline__ void ldsm4(uint32_t* r, uint32_t a) {
    asm volatile("ldmatrix.sync.aligned.m8n8.x4.shared.b16 {%0,%1,%2,%3}, [%4];"
                 : "=r"(r[0]), "=r"(r[1]), "=r"(r[2]), "=r"(r[3]) : "r"(a));
}
__device__ __forceinline__ void mma16816(float* d, const uint32_t* a,
                                         uint32_t b0, uint32_t b1) {
    asm volatile("mma.sync.aligned.m16n8k16.row.col.f32.bf16.bf16.f32 "
                 "{%0,%1,%2,%3}, {%4,%5,%6,%7}, {%8,%9}, {%0,%1,%2,%3};"
                 : "+f"(d[0]), "+f"(d[1]), "+f"(d[2]), "+f"(d[3])
                 : "r"(a[0]), "r"(a[1]), "r"(a[2]), "r"(a[3]), "r"(b0), "r"(b1));
}
__device__ __forceinline__ uint32_t pack_bf16(__nv_bfloat16 lo, __nv_bfloat16 hi) {
    return ((uint32_t)__bfloat16_as_ushort(hi) << 16) | __bfloat16_as_ushort(lo);
}

// ---------------- tiny kernels ----------------------------------------------
__global__ void zero_stats_kernel() {
    g_sum[threadIdx.x] = 0.0f;
    g_sumsq[threadIdx.x] = 0.0f;
}

__global__ void bn_scale_kernel(const float* __restrict__ g,
                                const float* __restrict__ be) {
    int c = threadIdx.x;
    const float inv = 1.0f / (float)MROWS;
    float mu  = g_sum[c] * inv;
    float var = g_sumsq[c] * inv - mu * mu;
    float s   = g[c] * rsqrtf(var + EPS);
    g_scale[c] = s;
    g_shift[c] = be[c] - mu * s;
    g_sum[c] = 0.0f;
    g_sumsq[c] = 0.0f;
}

// transpose + hi/lo bf16 split of all 4 weight matrices: Wt[n][k] = W[k][n]
__global__ void prep_w_kernel(const float* __restrict__ W1, const float* __restrict__ W2,
                              const float* __restrict__ W3, const float* __restrict__ W4) {
    const float* W = (blockIdx.y == 0) ? W1 : (blockIdx.y == 1) ? W2
                     : (blockIdx.y == 2) ? W3 : W4;
    int k = blockIdx.x, n = threadIdx.x;
    float v = W[k * D + n];
    __nv_bfloat16 h = __float2bfloat16(v);
    float lo = v - __bfloat162float(h);
    size_t o = (size_t)blockIdx.y * D * D + (size_t)n * D + k;
    g_wh[o] = h;
    g_wl[o] = __float2bfloat16(lo);
}

// ---------------- shared layout (static: <=48KB, no attrs needed) ----------
struct __align__(16) SmemLayout {
    char  A[2][2][BM * ARB];   // [buf][hi/lo]  2*2*6144 = 24576
    char  B[2][2][BN * BRB];   // [buf][hi/lo]  2*2*3072 = 12288
    float bias[BN];
    float scale[D];
    float shift[D];
    int   ids[BM];
    float stat[2 * BN];
};

// ---------------- fused GEMM(3x bf16 mma) + affine-A + bias + GELU + stats --
// SRC: 0=g_x0, 1=g_x1, 2=gather(table, ids)   DST: 0=g_x0, 1=g_x1, 2=ext_out
template<int SRC, int DST, bool AFFINE, bool STATS>
__global__ __launch_bounds__(256, 2)
void layer_kernel(const float* __restrict__ table, const int* __restrict__ ids,
                  int layer, const float* __restrict__ bias,
                  float* __restrict__ ext_out)
{
    __shared__ SmemLayout sm;

    const float* __restrict__ Asrc = (SRC == 0) ? g_x0 : (SRC == 1) ? g_x1 : table;
    float*       __restrict__ Out  = (DST == 0) ? g_x0 : (DST == 1) ? g_x1 : ext_out;
    const __nv_bfloat16* __restrict__ WhP = g_wh + (size_t)layer * D * D;
    const __nv_bfloat16* __restrict__ WlP = g_wl + (size_t)layer * D * D;

    const int tid = threadIdx.x, lane = tid & 31, wid = tid >> 5;
    const int wm = wid & 3, wn = wid >> 2;          // warp grid 4(m) x 2(n)
    const int m0 = blockIdx.y * BM, n0 = blockIdx.x * BN;

    if (tid < BN) sm.bias[tid] = bias[n0 + tid];
    if (AFFINE) { sm.scale[tid] = g_scale[tid]; sm.shift[tid] = g_shift[tid]; }
    if (SRC == 2 && tid < BM) sm.ids[tid] = ids[m0 + tid];
    if (STATS && tid < 2 * BN) sm.stat[tid] = 0.0f;
    __syncthreads();

    // ---- global A mapping: row = tid>>1, k-half = (tid&1)*8 floats ----
    const int ar = tid >> 1, ah = tid & 1;
    const int grow = (SRC == 2) ? sm.ids[ar] : (m0 + ar);
    const float4* __restrict__ aG = (const float4*)(Asrc + (size_t)grow * D + ah * 8);

    // ---- global B mapping: tids 0-127 load hi part, 128-255 lo part ----
    const int bt = tid & 127;
    const int bn_ = bt >> 1, bc = bt & 1;
    const __nv_bfloat16* __restrict__ bG =
        ((tid < 128) ? WhP : WlP) + (size_t)(n0 + bn_) * D + bc * 8;

    char* aStH = &sm.A[0][0][ar * ARB + ah * 16];
    char* aStL = &sm.A[0][1][ar * ARB + ah * 16];
    char* bSt  = &sm.B[0][(tid < 128) ? 0 : 1][bn_ * BRB + bc * 16];

    // ---- ldmatrix base addresses (buf 0) ----
    uint32_t aRd0, bRd0;
    {
        const int rlo = (lane & 7) + ((lane >> 3) & 1) * 8;
        const int kb  = ((lane >> 4) & 1) * 16;
        aRd0 = smem_u32(&sm.A[0][0][0]) + (wm * 32 + rlo) * ARB + kb;
        bRd0 = smem_u32(&sm.B[0][0][0]) + (wn * 32 + rlo) * BRB + kb;
    }

    float4 aR0, aR1; uint4 bR;
    auto loadG = [&](int c) {
        aR0 = aG[c * 4];
        aR1 = aG[c * 4 + 1];
        bR  = *(const uint4*)(bG + c * 16);
    };
    auto storeS = [&](int buf, int c) {
        float v[8];
        *(float4*)&v[0] = aR0; *(float4*)&v[4] = aR1;
        const int kb = c * 16 + ah * 8;
        uint32_t hw[4], lw[4];
        #pragma unroll
        for (int j = 0; j < 4; j++) {
            float x0 = v[2 * j], x1 = v[2 * j + 1];
            if (AFFINE) {
                x0 = fmaf(x0, sm.scale[kb + 2 * j],     sm.shift[kb + 2 * j]);
                x1 = fmaf(x1, sm.scale[kb + 2 * j + 1], sm.shift[kb + 2 * j + 1]);
            }
            __nv_bfloat16 h0 = __float2bfloat16(x0), h1 = __float2bfloat16(x1);
            __nv_bfloat16 l0 = __float2bfloat16(x0 - __bfloat162float(h0));
            __nv_bfloat16 l1 = __float2bfloat16(x1 - __bfloat162float(h1));
            hw[j] = pack_bf16(h0, h1);
            lw[j] = pack_bf16(l0, l1);
        }
        *(uint4*)(aStH + buf * (int)sizeof(sm.A[0])) = make_uint4(hw[0], hw[1], hw[2], hw[3]);
        *(uint4*)(aStL + buf * (int)sizeof(sm.A[0])) = make_uint4(lw[0], lw[1], lw[2], lw[3]);
        *(uint4*)(bSt  + buf * (int)sizeof(sm.B[0])) = bR;
    };

    float acc[2][4][4];
    #pragma unroll
    for (int i = 0; i < 2; i++)
        #pragma unroll
        for (int j = 0; j < 4; j++)
            #pragma unroll
            for (int k = 0; k < 4; k++) acc[i][j][k] = 0.0f;

    loadG(0);
    storeS(0, 0);
    __syncthreads();

    #pragma unroll 1
    for (int c = 0; c < NCHUNK; c++) {
        const int buf = c & 1;
        if (c + 1 < NCHUNK) loadG(c + 1);

        uint32_t aH[2][4], aL[2][4], bH[2][4], bL[2][4];
        const uint32_t aB = aRd0 + buf * (uint32_t)sizeof(sm.A[0]);
        const uint32_t bB = bRd0 + buf * (uint32_t)sizeof(sm.B[0]);
        #pragma unroll
        for (int mi = 0; mi < 2; mi++) {
            ldsm4(aH[mi], aB + mi * (16 * ARB));
            ldsm4(aL[mi], aB + mi * (16 * ARB) + BM * ARB);
        }
        #pragma unroll
        for (int p = 0; p < 2; p++) {
            ldsm4(bH[p], bB + p * (16 * BRB));
            ldsm4(bL[p], bB + p * (16 * BRB) + BN * BRB);
        }

        // 3-pass split-bf16: Ah*Bh + Ah*Bl + Al*Bh  (Al*Bl ~2^-18, dropped)
        #pragma unroll
        for (int mi = 0; mi < 2; mi++)
            #pragma unroll
            for (int p = 0; p < 2; p++) {
                mma16816(acc[mi][2 * p],     aH[mi], bH[p][0], bH[p][2]);
                mma16816(acc[mi][2 * p + 1], aH[mi], bH[p][1], bH[p][3]);
                mma16816(acc[mi][2 * p],     aH[mi], bL[p][0], bL[p][2]);
                mma16816(acc[mi][2 * p + 1], aH[mi], bL[p][1], bL[p][3]);
                mma16816(acc[mi][2 * p],     aL[mi], bH[p][0], bH[p][2]);
                mma16816(acc[mi][2 * p + 1], aL[mi], bH[p][1], bH[p][3]);
            }

        if (c + 1 < NCHUNK) {
            __syncthreads();
            storeS(buf ^ 1, c + 1);
            __syncthreads();
        }
    }

    // ---- epilogue: bias + exact GELU + store (+ BN column stats) ----
    const int g = lane >> 2, t4 = lane & 3;
    float s_[4][2], q_[4][2];
    if (STATS) {
        #pragma unroll
        for (int ni = 0; ni < 4; ni++) { s_[ni][0] = s_[ni][1] = 0.f; q_[ni][0] = q_[ni][1] = 0.f; }
    }
    #pragma unroll
    for (int mi = 0; mi < 2; mi++) {
        const int row = m0 + wm * 32 + mi * 16 + g;
        #pragma unroll
        for (int ni = 0; ni < 4; ni++) {
            const int cl = wn * 32 + ni * 8 + t4 * 2;
            const float b0 = sm.bias[cl], b1 = sm.bias[cl + 1];
            float g0 = gelu_exact(acc[mi][ni][0] + b0);
            float g1 = gelu_exact(acc[mi][ni][1] + b1);
            float g2 = gelu_exact(acc[mi][ni][2] + b0);
            float g3 = gelu_exact(acc[mi][ni][3] + b1);
            *(float2*)(Out + (size_t)row * D + n0 + cl)       = make_float2(g0, g1);
            *(float2*)(Out + (size_t)(row + 8) * D + n0 + cl) = make_float2(g2, g3);
            if (STATS) {
                s_[ni][0] += g0 + g2;           s_[ni][1] += g1 + g3;
                q_[ni][0] += g0 * g0 + g2 * g2; q_[ni][1] += g1 * g1 + g3 * g3;
            }
        }
    }
    if (STATS) {
        #pragma unroll
        for (int ni = 0; ni < 4; ni++)
            #pragma unroll
            for (int j = 0; j < 2; j++) {
                float s = s_[ni][j], q = q_[ni][j];
                s += __shfl_xor_sync(0xffffffffu, s, 4);
                s += __shfl_xor_sync(0xffffffffu, s, 8);
                s += __shfl_xor_sync(0xffffffffu, s, 16);
                q += __shfl_xor_sync(0xffffffffu, q, 4);
                q += __shfl_xor_sync(0xffffffffu, q, 8);
                q += __shfl_xor_sync(0xffffffffu, q, 16);
                if (lane < 4) {
                    const int cl = wn * 32 + ni * 8 + 2 * lane + j;
                    atomicAdd(&sm.stat[cl], s);
                    atomicAdd(&sm.stat[BN + cl], q);
                }
            }
        __syncthreads();
        if (tid < BN)          atomicAdd(&g_sum[n0 + tid], sm.stat[tid]);
        else if (tid < 2 * BN) atomicAdd(&g_sumsq[n0 + tid - BN], sm.stat[tid]);
    }
}

// ---------------- launcher --------------------------------------------------
extern "C" void kernel_launch(void* const* d_in, const int* in_sizes, int n_in,
                              void* d_out, int out_size)
{
    const int*   ids   = (const int*)  d_in[0];
    const float* table = (const float*)d_in[1];
    const float* W1 = (const float*)d_in[2];  const float* b1 = (const float*)d_in[3];
    const float* W2 = (const float*)d_in[4];  const float* b2 = (const float*)d_in[5];
    const float* W3 = (const float*)d_in[6];  const float* b3 = (const float*)d_in[7];
    const float* W4 = (const float*)d_in[8];  const float* b4 = (const float*)d_in[9];
    const float* g1 = (const float*)d_in[10]; const float* be1 = (const float*)d_in[11];
    const float* g2 = (const float*)d_in[12]; const float* be2 = (const float*)d_in[13];
    const float* g3 = (const float*)d_in[14]; const float* be3 = (const float*)d_in[15];
    float* out = (float*)d_out;

    dim3 grid(D / BN, MROWS / BM);   // (4, 256) = 1024 CTAs
    dim3 blk(256);

    zero_stats_kernel<<<1, D>>>();
    prep_w_kernel<<<dim3(D, 4), D>>>(W1, W2, W3, W4);

    // L1: gather + GEMM(W1) + GELU, stats
    layer_kernel<2, 0, false, true><<<grid, blk>>>(table, ids, 0, b1, nullptr);
    bn_scale_kernel<<<1, D>>>(g1, be1);

    // L2: affine(x0) @ W2 + b2, GELU, stats
    layer_kernel<0, 1, true, true><<<grid, blk>>>(nullptr, nullptr, 1, b2, nullptr);
    bn_scale_kernel<<<1, D>>>(g2, be2);

    // L3
    layer_kernel<1, 0, true, true><<<grid, blk>>>(nullptr, nullptr, 2, b3, nullptr);
    bn_scale_kernel<<<1, D>>>(g3, be3);

    // L4 -> d_out, no stats
    layer_kernel<0, 2, true, false><<<grid, blk>>>(nullptr, nullptr, 3, b4, out);
}